// round 6
// baseline (speedup 1.0000x reference)
#include <cuda_runtime.h>
#include <math.h>

// ---------------- problem constants ----------------
#define EMBEDD 512
#define DEPTHN 6
#define NSTATE 16
#define DCONVN 4
#define DTRN   32
#define VOCABN 50000
#define BBATCH 2
#define LSEQ   1024
#define MLPDIM 2048
#define ROWS   (BBATCH * LSEQ)      // 2048
#define PDIM   (DTRN + 2 * NSTATE)  // 64

// ---------------- scratch (static device, no allocs) ----------------
__device__ float g_x   [ROWS * EMBEDD];
__device__ float g_h   [ROWS * EMBEDD];
__device__ float g_xp  [ROWS * EMBEDD];
__device__ float g_z   [ROWS * EMBEDD];
__device__ float g_p   [ROWS * PDIM];
__device__ float g_dt  [ROWS * EMBEDD];
__device__ float g_u   [ROWS * EMBEDD];
__device__ float g_y   [ROWS * EMBEDD];
__device__ float g_mlp [ROWS * MLPDIM];
__device__ float g_feat[BBATCH * EMBEDD];
__device__ float g_h1  [BBATCH * MLPDIM];
__device__ float g_te  [BBATCH * EMBEDD];

// ---------------- helpers ----------------
__device__ __forceinline__ float siluf(float x) {
    return x / (1.0f + expf(-x));
}
__device__ __forceinline__ float geluf(float x) {
    return 0.5f * x * (1.0f + erff(x * 0.70710678118654752f));
}
__device__ __forceinline__ float softplusf(float x) {
    return fmaxf(x, 0.0f) + log1pf(expf(-fabsf(x)));
}

// ---------------- time embedding ----------------
__global__ void time_feat_kernel(const int* __restrict__ t) {
    int e = threadIdx.x;  // 512
    const int half = EMBEDD / 2;
    int j = (e < half) ? e : (e - half);
    float freq = expf((float)j * (-logf(10000.0f) / (float)(half - 1)));
    for (int b = 0; b < BBATCH; b++) {
        float a = (float)t[b] * freq;
        g_feat[b * EMBEDD + e] = (e < half) ? sinf(a) : cosf(a);
    }
}

__global__ void time_mlp1_kernel(const float* __restrict__ w1, const float* __restrict__ b1) {
    int gid = blockIdx.x * blockDim.x + threadIdx.x;  // BBATCH*MLPDIM
    if (gid >= BBATCH * MLPDIM) return;
    int b = gid / MLPDIM;
    int o = gid % MLPDIM;
    float acc = b1[o];
    #pragma unroll 8
    for (int k = 0; k < EMBEDD; k++)
        acc += g_feat[b * EMBEDD + k] * w1[k * MLPDIM + o];
    g_h1[gid] = siluf(acc);
}

__global__ void time_mlp2_kernel(const float* __restrict__ w2, const float* __restrict__ b2) {
    int gid = blockIdx.x * blockDim.x + threadIdx.x;  // BBATCH*EMBEDD
    if (gid >= BBATCH * EMBEDD) return;
    int b = gid / EMBEDD;
    int e = gid % EMBEDD;
    float acc = b2[e];
    #pragma unroll 8
    for (int k = 0; k < MLPDIM; k++)
        acc += g_h1[b * MLPDIM + k] * w2[k * EMBEDD + e];
    g_te[gid] = acc;
}

// ---------------- embedding ----------------
__global__ void embed_kernel(const int* __restrict__ tokens, const float* __restrict__ emb) {
    int row = blockIdx.x;     // ROWS
    int e   = threadIdx.x;    // 512
    int b   = row / LSEQ;
    int tok = tokens[row];
    g_x[row * EMBEDD + e] = emb[tok * EMBEDD + e] + g_te[b * EMBEDD + e];
}

// ---------------- layernorm (one block per row, 512 threads) ----------------
__global__ void ln_kernel(const float* __restrict__ in, float* __restrict__ out,
                          const float* __restrict__ s, const float* __restrict__ bia) {
    int row = blockIdx.x;
    int e = threadIdx.x;
    float v = in[row * EMBEDD + e];
    float sum = v, sq = v * v;
    #pragma unroll
    for (int m = 16; m; m >>= 1) {
        sum += __shfl_xor_sync(0xffffffffu, sum, m);
        sq  += __shfl_xor_sync(0xffffffffu, sq, m);
    }
    __shared__ float s1[16], s2[16];
    __shared__ float mv, rv;
    int wid = e >> 5, lane = e & 31;
    if (lane == 0) { s1[wid] = sum; s2[wid] = sq; }
    __syncthreads();
    if (e == 0) {
        float ts = 0.f, tq = 0.f;
        #pragma unroll
        for (int i = 0; i < 16; i++) { ts += s1[i]; tq += s2[i]; }
        float m = ts / (float)EMBEDD;
        float var = tq / (float)EMBEDD - m * m;
        mv = m;
        rv = rsqrtf(var + 1e-5f);
    }
    __syncthreads();
    out[row * EMBEDD + e] = (v - mv) * rv * s[e] + bia[e];
}

// ---------------- fp32 SIMT GEMM, 64x64 tile, 4x4/thread, double-buffered ----------------
// C = act(A@B + bias) + resid.  M%64==0, K%16==0, N%4==0. act: 0 none, 1 gelu
__global__ void gemm_kernel(const float* __restrict__ A, const float* __restrict__ Bm,
                            const float* __restrict__ bias, const float* __restrict__ resid,
                            float* __restrict__ C, int M, int N, int K, int act) {
    __shared__ float As[2][16][64];
    __shared__ float Bs[2][16][64];
    int tid = threadIdx.x;            // 256
    int tx = tid & 15, ty = tid >> 4; // 16x16
    int n0 = blockIdx.x * 64;
    int m0 = blockIdx.y * 64;

    float acc[4][4] = {};

    int arow = tid >> 2;              // 0..63
    int aseg = (tid & 3) * 4;         // 0,4,8,12
    int brow = tid >> 4;              // 0..15
    int bcol = (tid & 15) * 4;        // 0..60

    const float* Aptr = &A[(size_t)(m0 + arow) * K + aseg];
    const float* Bptr = &Bm[(size_t)brow * N + n0 + bcol];
    bool bok = (n0 + bcol < N);

    // preload tile 0
    {
        float4 av = *(const float4*)Aptr;
        As[0][aseg + 0][arow] = av.x;
        As[0][aseg + 1][arow] = av.y;
        As[0][aseg + 2][arow] = av.z;
        As[0][aseg + 3][arow] = av.w;
        float4 bv = make_float4(0.f, 0.f, 0.f, 0.f);
        if (bok) bv = *(const float4*)Bptr;
        *(float4*)&Bs[0][brow][bcol] = bv;
    }
    __syncthreads();

    int cur = 0;
    for (int k0 = 0; k0 < K; k0 += 16) {
        float4 av, bv;
        bool have_next = (k0 + 16 < K);
        if (have_next) {
            av = *(const float4*)(Aptr + k0 + 16);
            bv = make_float4(0.f, 0.f, 0.f, 0.f);
            if (bok) bv = *(const float4*)(Bptr + (size_t)(k0 + 16) * N);
        }
        #pragma unroll
        for (int kk = 0; kk < 16; kk++) {
            float a[4], b[4];
            *(float4*)a = *(const float4*)&As[cur][kk][ty * 4];
            *(float4*)b = *(const float4*)&Bs[cur][kk][tx * 4];
            #pragma unroll
            for (int i = 0; i < 4; i++)
                #pragma unroll
                for (int j = 0; j < 4; j++)
                    acc[i][j] += a[i] * b[j];
        }
        if (have_next) {
            int nxt = cur ^ 1;
            As[nxt][aseg + 0][arow] = av.x;
            As[nxt][aseg + 1][arow] = av.y;
            As[nxt][aseg + 2][arow] = av.z;
            As[nxt][aseg + 3][arow] = av.w;
            *(float4*)&Bs[nxt][brow][bcol] = bv;
            __syncthreads();
            cur = nxt;
        }
    }

    int col0 = n0 + tx * 4;
    if (col0 < N) {
        float4 bv4 = make_float4(0.f, 0.f, 0.f, 0.f);
        if (bias) bv4 = *(const float4*)&bias[col0];
        #pragma unroll
        for (int i = 0; i < 4; i++) {
            int row = m0 + ty * 4 + i;
            float4 v = make_float4(acc[i][0] + bv4.x, acc[i][1] + bv4.y,
                                   acc[i][2] + bv4.z, acc[i][3] + bv4.w);
            if (act == 1) {
                v.x = geluf(v.x); v.y = geluf(v.y);
                v.z = geluf(v.z); v.w = geluf(v.w);
            }
            if (resid) {
                float4 r = *(const float4*)&resid[(size_t)row * N + col0];
                v.x += r.x; v.y += r.y; v.z += r.z; v.w += r.w;
            }
            *(float4*)&C[(size_t)row * N + col0] = v;
        }
    }
}

// ---------------- fused dual GEMM: C0 = A@B0, C1 = A@B1 (shared A tile) ----------------
// 64x64 tile, 4x4x2 per thread, double-buffered. M%64==0, N%64==0, K%16==0.
__global__ void gemm2_kernel(const float* __restrict__ A,
                             const float* __restrict__ B0, const float* __restrict__ B1,
                             float* __restrict__ C0, float* __restrict__ C1,
                             int M, int N, int K) {
    __shared__ float As [2][16][64];
    __shared__ float Bs0[2][16][64];
    __shared__ float Bs1[2][16][64];
    int tid = threadIdx.x;            // 256
    int tx = tid & 15, ty = tid >> 4; // 16x16
    int n0 = blockIdx.x * 64;
    int m0 = blockIdx.y * 64;

    float acc0[4][4] = {};
    float acc1[4][4] = {};

    int arow = tid >> 2;              // 0..63
    int aseg = (tid & 3) * 4;         // 0,4,8,12
    int brow = tid >> 4;              // 0..15
    int bcol = (tid & 15) * 4;        // 0..60

    const float* Aptr  = &A [(size_t)(m0 + arow) * K + aseg];
    const float* Bptr0 = &B0[(size_t)brow * N + n0 + bcol];
    const float* Bptr1 = &B1[(size_t)brow * N + n0 + bcol];

    // preload tile 0
    {
        float4 av = *(const float4*)Aptr;
        As[0][aseg + 0][arow] = av.x;
        As[0][aseg + 1][arow] = av.y;
        As[0][aseg + 2][arow] = av.z;
        As[0][aseg + 3][arow] = av.w;
        *(float4*)&Bs0[0][brow][bcol] = *(const float4*)Bptr0;
        *(float4*)&Bs1[0][brow][bcol] = *(const float4*)Bptr1;
    }
    __syncthreads();

    int cur = 0;
    for (int k0 = 0; k0 < K; k0 += 16) {
        float4 av, bv0, bv1;
        bool have_next = (k0 + 16 < K);
        if (have_next) {
            av  = *(const float4*)(Aptr  + k0 + 16);
            bv0 = *(const float4*)(Bptr0 + (size_t)(k0 + 16) * N);
            bv1 = *(const float4*)(Bptr1 + (size_t)(k0 + 16) * N);
        }
        #pragma unroll
        for (int kk = 0; kk < 16; kk++) {
            float a[4], b0[4], b1[4];
            *(float4*)a  = *(const float4*)&As [cur][kk][ty * 4];
            *(float4*)b0 = *(const float4*)&Bs0[cur][kk][tx * 4];
            *(float4*)b1 = *(const float4*)&Bs1[cur][kk][tx * 4];
            #pragma unroll
            for (int i = 0; i < 4; i++)
                #pragma unroll
                for (int j = 0; j < 4; j++) {
                    acc0[i][j] += a[i] * b0[j];
                    acc1[i][j] += a[i] * b1[j];
                }
        }
        if (have_next) {
            int nxt = cur ^ 1;
            As[nxt][aseg + 0][arow] = av.x;
            As[nxt][aseg + 1][arow] = av.y;
            As[nxt][aseg + 2][arow] = av.z;
            As[nxt][aseg + 3][arow] = av.w;
            *(float4*)&Bs0[nxt][brow][bcol] = bv0;
            *(float4*)&Bs1[nxt][brow][bcol] = bv1;
            __syncthreads();
            cur = nxt;
        }
    }

    int col0 = n0 + tx * 4;
    #pragma unroll
    for (int i = 0; i < 4; i++) {
        int row = m0 + ty * 4 + i;
        float4 v0 = make_float4(acc0[i][0], acc0[i][1], acc0[i][2], acc0[i][3]);
        float4 v1 = make_float4(acc1[i][0], acc1[i][1], acc1[i][2], acc1[i][3]);
        *(float4*)&C0[(size_t)row * N + col0] = v0;
        *(float4*)&C1[(size_t)row * N + col0] = v1;
    }
}

// ---------------- fp32 SIMT GEMM, 128x128 tile, 8x8/thread, double-buffered ----------------
// C = act(A@B + bias).  M%128==0, K%8==0, N%4==0. For large-grid GEMMs
// (vocab head, mlp1). act: 0 none, 1 gelu
__global__ void __launch_bounds__(256, 2)
gemm128_kernel(const float* __restrict__ A, const float* __restrict__ Bm,
               const float* __restrict__ bias, float* __restrict__ C,
               int M, int N, int K, int act) {
    __shared__ float As[2][8][128];
    __shared__ float Bs[2][8][128];
    int tid = threadIdx.x;            // 256
    int tx = tid & 15, ty = tid >> 4; // 16x16
    int n0 = blockIdx.x * 128;
    int m0 = blockIdx.y * 128;

    float acc[8][8] = {};

    int am = tid >> 1;           // 0..127
    int ak = (tid & 1) * 4;      // 0 or 4
    int bk = tid >> 5;           // 0..7
    int bn = (tid & 31) * 4;     // 0..124

    const float* Aptr = &A[(size_t)(m0 + am) * K + ak];
    const float* Bptr = &Bm[(size_t)bk * N + n0 + bn];
    bool bok = (n0 + bn < N);

    // preload tile 0
    {
        float4 av = *(const float4*)Aptr;
        As[0][ak + 0][am] = av.x;
        As[0][ak + 1][am] = av.y;
        As[0][ak + 2][am] = av.z;
        As[0][ak + 3][am] = av.w;
        float4 bv = make_float4(0.f, 0.f, 0.f, 0.f);
        if (bok) bv = *(const float4*)Bptr;
        *(float4*)&Bs[0][bk][bn] = bv;
    }
    __syncthreads();

    int cur = 0;
    for (int k0 = 0; k0 < K; k0 += 8) {
        // prefetch next tile into registers while computing on cur
        float4 av, bv;
        bool have_next = (k0 + 8 < K);
        if (have_next) {
            av = *(const float4*)(Aptr + k0 + 8);
            bv = make_float4(0.f, 0.f, 0.f, 0.f);
            if (bok) bv = *(const float4*)(Bptr + (size_t)(k0 + 8) * N);
        }
        #pragma unroll
        for (int kk = 0; kk < 8; kk++) {
            float a[8], b[8];
            *(float4*)&a[0] = *(const float4*)&As[cur][kk][ty * 4];
            *(float4*)&a[4] = *(const float4*)&As[cur][kk][64 + ty * 4];
            *(float4*)&b[0] = *(const float4*)&Bs[cur][kk][tx * 4];
            *(float4*)&b[4] = *(const float4*)&Bs[cur][kk][64 + tx * 4];
            #pragma unroll
            for (int i = 0; i < 8; i++)
                #pragma unroll
                for (int j = 0; j < 8; j++)
                    acc[i][j] += a[i] * b[j];
        }
        if (have_next) {
            int nxt = cur ^ 1;
            As[nxt][ak + 0][am] = av.x;
            As[nxt][ak + 1][am] = av.y;
            As[nxt][ak + 2][am] = av.z;
            As[nxt][ak + 3][am] = av.w;
            *(float4*)&Bs[nxt][bk][bn] = bv;
            __syncthreads();
            cur = nxt;
        }
    }

    #pragma unroll
    for (int jh = 0; jh < 2; jh++) {
        int col = n0 + jh * 64 + tx * 4;
        if (col >= N) continue;
        float4 bv4 = make_float4(0.f, 0.f, 0.f, 0.f);
        if (bias) bv4 = *(const float4*)&bias[col];
        #pragma unroll
        for (int ih = 0; ih < 2; ih++) {
            #pragma unroll
            for (int i = 0; i < 4; i++) {
                int row = m0 + ih * 64 + ty * 4 + i;
                float4 v = make_float4(acc[ih * 4 + i][jh * 4 + 0] + bv4.x,
                                       acc[ih * 4 + i][jh * 4 + 1] + bv4.y,
                                       acc[ih * 4 + i][jh * 4 + 2] + bv4.z,
                                       acc[ih * 4 + i][jh * 4 + 3] + bv4.w);
                if (act == 1) {
                    v.x = geluf(v.x); v.y = geluf(v.y);
                    v.z = geluf(v.z); v.w = geluf(v.w);
                }
                *(float4*)&C[(size_t)row * N + col] = v;
            }
        }
    }
}

// ---------------- dt = softplus(p[:, :32] @ dt_w + dt_b) ----------------
__global__ void dt_kernel(const float* __restrict__ dt_w, const float* __restrict__ dt_b) {
    int row = blockIdx.x;   // ROWS
    int e = threadIdx.x;    // 512
    const float* pr = &g_p[row * PDIM];
    float acc = dt_b[e];
    #pragma unroll
    for (int r = 0; r < DTRN; r++)
        acc += pr[r] * dt_w[r * EMBEDD + e];
    g_dt[row * EMBEDD + e] = softplusf(acc);
}

// ---------------- depthwise causal conv (DCONV=4) + silu ----------------
__global__ void conv_kernel(const float* __restrict__ cw) {
    int row = blockIdx.x;
    int e = threadIdx.x;
    int b = row / LSEQ, l = row % LSEQ;
    float acc = 0.f;
    #pragma unroll
    for (int k = 0; k < DCONVN; k++) {
        int lsrc = l - (DCONVN - 1) + k;
        if (lsrc >= 0)
            acc += g_xp[(b * LSEQ + lsrc) * EMBEDD + e] * cw[e * DCONVN + k];
    }
    g_u[row * EMBEDD + e] = siluf(acc);
}

// ---------------- SSM scan with shared-memory staging ----------------
// Block = 128 threads: one batch b, 8 consecutive d channels, 16 n states each.
// Grid = BBATCH * (EMBEDD/8) = 128 blocks.
// Stages TCHUNK=64 timesteps of Bp/Cp (shared by all 8 d-groups) and dt/u
// into smem with coalesced loads, then runs the serial recurrence from smem.
#define TCHUNK 64
__global__ void __launch_bounds__(128)
scan_kernel(const float* __restrict__ A_log, const float* __restrict__ Dparam) {
    __shared__ float sB [TCHUNK][NSTATE];   // 4KB
    __shared__ float sC [TCHUNK][NSTATE];   // 4KB
    __shared__ float sdt[TCHUNK][8];        // 2KB
    __shared__ float su [TCHUNK][8];        // 2KB

    int tid  = threadIdx.x;
    int n    = tid & 15;        // state index
    int dloc = tid >> 4;        // 0..7
    int b    = blockIdx.x / (EMBEDD / 8);
    int d0   = (blockIdx.x % (EMBEDD / 8)) * 8;
    int d    = d0 + dloc;

    float A = -expf(A_log[d * NSTATE + n]);
    float Ainv = 1.0f / (A + 1e-8f);
    float Dp = Dparam[d];
    float h = 0.0f;

    for (int t0 = 0; t0 < LSEQ; t0 += TCHUNK) {
        __syncthreads();  // protect previous chunk's smem from overwrite
        // stage Bp/Cp: TCHUNK*16 elements each, 128 threads -> 8 iters
        #pragma unroll
        for (int idx = tid; idx < TCHUNK * NSTATE; idx += 128) {
            int tt = idx >> 4, nn = idx & 15;
            int rowi = b * LSEQ + t0 + tt;
            sB[tt][nn] = g_p[rowi * PDIM + DTRN + nn];
            sC[tt][nn] = g_p[rowi * PDIM + DTRN + NSTATE + nn];
        }
        // stage dt/u: TCHUNK*8 elements each, 128 threads -> 4 iters
        #pragma unroll
        for (int idx = tid; idx < TCHUNK * 8; idx += 128) {
            int tt = idx >> 3, dl = idx & 7;
            int rowi = b * LSEQ + t0 + tt;
            sdt[tt][dl] = g_dt[rowi * EMBEDD + d0 + dl];
            su [tt][dl] = g_u [rowi * EMBEDD + d0 + dl];
        }
        __syncthreads();

        for (int tt = 0; tt < TCHUNK; tt++) {
            float dtv = sdt[tt][dloc];
            float uv  = su [tt][dloc];
            float Bp  = sB [tt][n];
            float Cp  = sC [tt][n];
            float At = expf(A * dtv);
            float Bt = (At - 1.0f) * Ainv;
            h = At * h + Bt * Bp * uv;
            float c = Cp * h;
            c += __shfl_xor_sync(0xffffffffu, c, 8, 16);
            c += __shfl_xor_sync(0xffffffffu, c, 4, 16);
            c += __shfl_xor_sync(0xffffffffu, c, 2, 16);
            c += __shfl_xor_sync(0xffffffffu, c, 1, 16);
            if (n == 0) {
                int rowi = b * LSEQ + t0 + tt;
                float yv = c + uv * Dp;
                float zv = g_z[rowi * EMBEDD + d];
                g_y[rowi * EMBEDD + d] = yv * siluf(zv);
            }
        }
    }
}

// ---------------- host launcher ----------------
extern "C" void kernel_launch(void* const* d_in, const int* in_sizes, int n_in,
                              void* d_out, int out_size) {
    const int*   tokens  = (const int*)  d_in[0];
    const int*   t       = (const int*)  d_in[1];
    const float* tok_emb = (const float*)d_in[2];
    const float* time_w1 = (const float*)d_in[3];
    const float* time_b1 = (const float*)d_in[4];
    const float* time_w2 = (const float*)d_in[5];
    const float* time_b2 = (const float*)d_in[6];
    const float* n1_s    = (const float*)d_in[7];
    const float* n1_b    = (const float*)d_in[8];
    const float* wx      = (const float*)d_in[9];
    const float* wz      = (const float*)d_in[10];
    const float* wp      = (const float*)d_in[11];
    const float* conv_w  = (const float*)d_in[12];
    const float* dt_w    = (const float*)d_in[13];
    const float* dt_b    = (const float*)d_in[14];
    const float* A_log   = (const float*)d_in[15];
    const float* Dparam  = (const float*)d_in[16];
    const float* wo      = (const float*)d_in[17];
    const float* n2_s    = (const float*)d_in[18];
    const float* n2_b    = (const float*)d_in[19];
    const float* mlp_w1  = (const float*)d_in[20];
    const float* mlp_b1  = (const float*)d_in[21];
    const float* mlp_w2  = (const float*)d_in[22];
    const float* mlp_b2  = (const float*)d_in[23];
    const float* no_s    = (const float*)d_in[24];
    const float* no_b    = (const float*)d_in[25];
    const float* head_w  = (const float*)d_in[26];
    const float* head_b  = (const float*)d_in[27];
    float* out = (float*)d_out;

    float *px, *ph, *pxp, *pz, *pp, *py, *pmlp;
    cudaGetSymbolAddress((void**)&px,   g_x);
    cudaGetSymbolAddress((void**)&ph,   g_h);
    cudaGetSymbolAddress((void**)&pxp,  g_xp);
    cudaGetSymbolAddress((void**)&pz,   g_z);
    cudaGetSymbolAddress((void**)&pp,   g_p);
    cudaGetSymbolAddress((void**)&py,   g_y);
    cudaGetSymbolAddress((void**)&pmlp, g_mlp);

    // time embedding + token embedding
    time_feat_kernel<<<1, EMBEDD>>>(t);
    time_mlp1_kernel<<<(BBATCH * MLPDIM + 255) / 256, 256>>>(time_w1, time_b1);
    time_mlp2_kernel<<<(BBATCH * EMBEDD + 255) / 256, 256>>>(time_w2, time_b2);
    embed_kernel<<<ROWS, EMBEDD>>>(tokens, tok_emb);

    dim3 gE((EMBEDD + 63) / 64, ROWS / 64);       // 64-tile, N=512  (grid 8x32)
    dim3 gP((PDIM   + 63) / 64, ROWS / 64);       // 64-tile, N=64   (grid 1x32)
    dim3 gM((MLPDIM + 127) / 128, ROWS / 128);    // 128-tile, N=2048 (grid 16x16)
    dim3 gV((VOCABN + 127) / 128, ROWS / 128);    // 128-tile, N=50000 (grid 391x16)

    for (int i = 0; i < DEPTHN; i++) {
        // ln1
        ln_kernel<<<ROWS, EMBEDD>>>(px, ph, n1_s + i * EMBEDD, n1_b + i * EMBEDD);
        // fused xp/z projections (shared A tiles)
        gemm2_kernel<<<gE, 256>>>(ph, wx + (size_t)i * EMBEDD * EMBEDD,
                                      wz + (size_t)i * EMBEDD * EMBEDD,
                                      pxp, pz, ROWS, EMBEDD, EMBEDD);
        // p projection
        gemm_kernel<<<gP, 256>>>(ph, wp + (size_t)i * EMBEDD * PDIM,   nullptr, nullptr, pp,  ROWS, PDIM,   EMBEDD, 0);
        // dt projection + softplus
        dt_kernel<<<ROWS, EMBEDD>>>(dt_w + (size_t)i * DTRN * EMBEDD, dt_b + i * EMBEDD);
        // causal depthwise conv + silu
        conv_kernel<<<ROWS, EMBEDD>>>(conv_w + (size_t)i * EMBEDD * DCONVN);
        // selective scan + gate (smem-staged)
        scan_kernel<<<BBATCH * (EMBEDD / 8), 128>>>(A_log + (size_t)i * EMBEDD * NSTATE,
                                                    Dparam + i * EMBEDD);
        // out projection + residual (x = x + y @ wo)
        gemm_kernel<<<gE, 256>>>(py, wo + (size_t)i * EMBEDD * EMBEDD, nullptr, px, px, ROWS, EMBEDD, EMBEDD, 0);
        // ln2 + MLP
        ln_kernel<<<ROWS, EMBEDD>>>(px, ph, n2_s + i * EMBEDD, n2_b + i * EMBEDD);
        gemm128_kernel<<<gM, 256>>>(ph, mlp_w1 + (size_t)i * EMBEDD * MLPDIM, mlp_b1 + i * MLPDIM, pmlp, ROWS, MLPDIM, EMBEDD, 1);
        gemm_kernel<<<gE, 256>>>(pmlp, mlp_w2 + (size_t)i * MLPDIM * EMBEDD, mlp_b2 + i * EMBEDD, px, px, ROWS, EMBEDD, MLPDIM, 0);
    }

    // final LN + vocab head
    ln_kernel<<<ROWS, EMBEDD>>>(px, ph, no_s, no_b);
    gemm128_kernel<<<gV, 256>>>(ph, head_w, head_b, out, ROWS, VOCABN, EMBEDD, 0);
}

// round 8
// speedup vs baseline: 1.0160x; 1.0160x over previous
#include <cuda_runtime.h>
#include <math.h>
#include <stdint.h>

// ---------------- problem constants ----------------
#define EMBEDD 512
#define DEPTHN 6
#define NSTATE 16
#define DCONVN 4
#define DTRN   32
#define VOCABN 50000
#define BBATCH 2
#define LSEQ   1024
#define MLPDIM 2048
#define ROWS   (BBATCH * LSEQ)      // 2048
#define PDIM   (DTRN + 2 * NSTATE)  // 64

// ---------------- scratch (static device, no allocs) ----------------
__device__ float g_x   [ROWS * EMBEDD];
__device__ float g_h   [ROWS * EMBEDD];
__device__ float g_xp  [ROWS * EMBEDD];
__device__ float g_z   [ROWS * EMBEDD];
__device__ float g_p   [ROWS * PDIM];
__device__ float g_dt  [ROWS * EMBEDD];
__device__ float g_u   [ROWS * EMBEDD];
__device__ float g_y   [ROWS * EMBEDD];
__device__ float g_mlp [ROWS * MLPDIM];
__device__ float g_feat[BBATCH * EMBEDD];
__device__ float g_h1  [BBATCH * MLPDIM];
__device__ float g_te  [BBATCH * EMBEDD];

// ---------------- helpers ----------------
__device__ __forceinline__ float siluf(float x) {
    return x / (1.0f + expf(-x));
}
__device__ __forceinline__ float geluf(float x) {
    return 0.5f * x * (1.0f + erff(x * 0.70710678118654752f));
}
__device__ __forceinline__ float softplusf(float x) {
    return fmaxf(x, 0.0f) + log1pf(expf(-fabsf(x)));
}

// tf32 split: v = hi + lo, both representable in tf32 (bit patterns in u32)
__device__ __forceinline__ void tf32_split(float v, uint32_t& hi, uint32_t& lo) {
    uint32_t h;
    asm("cvt.rna.tf32.f32 %0, %1;" : "=r"(h) : "f"(v));
    float lv = v - __uint_as_float(h);
    uint32_t l;
    asm("cvt.rna.tf32.f32 %0, %1;" : "=r"(l) : "f"(lv));
    hi = h; lo = l;
}

__device__ __forceinline__ void mma_tf32(float* d, const uint32_t* a, const uint32_t* b) {
    asm volatile(
        "mma.sync.aligned.m16n8k8.row.col.f32.tf32.tf32.f32 "
        "{%0,%1,%2,%3}, {%4,%5,%6,%7}, {%8,%9}, {%0,%1,%2,%3};\n"
        : "+f"(d[0]), "+f"(d[1]), "+f"(d[2]), "+f"(d[3])
        : "r"(a[0]), "r"(a[1]), "r"(a[2]), "r"(a[3]),
          "r"(b[0]), "r"(b[1]));
}

// ---------------- time embedding ----------------
__global__ void time_feat_kernel(const int* __restrict__ t) {
    int e = threadIdx.x;  // 512
    const int half = EMBEDD / 2;
    int j = (e < half) ? e : (e - half);
    float freq = expf((float)j * (-logf(10000.0f) / (float)(half - 1)));
    for (int b = 0; b < BBATCH; b++) {
        float a = (float)t[b] * freq;
        g_feat[b * EMBEDD + e] = (e < half) ? sinf(a) : cosf(a);
    }
}

__global__ void time_mlp1_kernel(const float* __restrict__ w1, const float* __restrict__ b1) {
    int gid = blockIdx.x * blockDim.x + threadIdx.x;  // BBATCH*MLPDIM
    if (gid >= BBATCH * MLPDIM) return;
    int b = gid / MLPDIM;
    int o = gid % MLPDIM;
    float acc = b1[o];
    #pragma unroll 8
    for (int k = 0; k < EMBEDD; k++)
        acc += g_feat[b * EMBEDD + k] * w1[k * MLPDIM + o];
    g_h1[gid] = siluf(acc);
}

__global__ void time_mlp2_kernel(const float* __restrict__ w2, const float* __restrict__ b2) {
    int gid = blockIdx.x * blockDim.x + threadIdx.x;  // BBATCH*EMBEDD
    if (gid >= BBATCH * EMBEDD) return;
    int b = gid / EMBEDD;
    int e = gid % EMBEDD;
    float acc = b2[e];
    #pragma unroll 8
    for (int k = 0; k < MLPDIM; k++)
        acc += g_h1[b * MLPDIM + k] * w2[k * EMBEDD + e];
    g_te[gid] = acc;
}

// ---------------- embedding ----------------
__global__ void embed_kernel(const int* __restrict__ tokens, const float* __restrict__ emb) {
    int row = blockIdx.x;     // ROWS
    int e   = threadIdx.x;    // 512
    int b   = row / LSEQ;
    int tok = tokens[row];
    g_x[row * EMBEDD + e] = emb[tok * EMBEDD + e] + g_te[b * EMBEDD + e];
}

// ---------------- layernorm (one block per row, 512 threads) ----------------
__global__ void ln_kernel(const float* __restrict__ in, float* __restrict__ out,
                          const float* __restrict__ s, const float* __restrict__ bia) {
    int row = blockIdx.x;
    int e = threadIdx.x;
    float v = in[row * EMBEDD + e];
    float sum = v, sq = v * v;
    #pragma unroll
    for (int m = 16; m; m >>= 1) {
        sum += __shfl_xor_sync(0xffffffffu, sum, m);
        sq  += __shfl_xor_sync(0xffffffffu, sq, m);
    }
    __shared__ float s1[16], s2[16];
    __shared__ float mv, rv;
    int wid = e >> 5, lane = e & 31;
    if (lane == 0) { s1[wid] = sum; s2[wid] = sq; }
    __syncthreads();
    if (e == 0) {
        float ts = 0.f, tq = 0.f;
        #pragma unroll
        for (int i = 0; i < 16; i++) { ts += s1[i]; tq += s2[i]; }
        float m = ts / (float)EMBEDD;
        float var = tq / (float)EMBEDD - m * m;
        mv = m;
        rv = rsqrtf(var + 1e-5f);
    }
    __syncthreads();
    out[row * EMBEDD + e] = (v - mv) * rv * s[e] + bia[e];
}

// ---------------- fp32 SIMT GEMM, 64x64 tile, 4x4/thread, double-buffered ----------------
// C = act(A@B + bias) + resid.  M%64==0, K%16==0, N%4==0. act: 0 none, 1 gelu
__global__ void gemm_kernel(const float* __restrict__ A, const float* __restrict__ Bm,
                            const float* __restrict__ bias, const float* __restrict__ resid,
                            float* __restrict__ C, int M, int N, int K, int act) {
    __shared__ float As[2][16][64];
    __shared__ float Bs[2][16][64];
    int tid = threadIdx.x;            // 256
    int tx = tid & 15, ty = tid >> 4; // 16x16
    int n0 = blockIdx.x * 64;
    int m0 = blockIdx.y * 64;

    float acc[4][4] = {};

    int arow = tid >> 2;              // 0..63
    int aseg = (tid & 3) * 4;         // 0,4,8,12
    int brow = tid >> 4;              // 0..15
    int bcol = (tid & 15) * 4;        // 0..60

    const float* Aptr = &A[(size_t)(m0 + arow) * K + aseg];
    const float* Bptr = &Bm[(size_t)brow * N + n0 + bcol];
    bool bok = (n0 + bcol < N);

    // preload tile 0
    {
        float4 av = *(const float4*)Aptr;
        As[0][aseg + 0][arow] = av.x;
        As[0][aseg + 1][arow] = av.y;
        As[0][aseg + 2][arow] = av.z;
        As[0][aseg + 3][arow] = av.w;
        float4 bv = make_float4(0.f, 0.f, 0.f, 0.f);
        if (bok) bv = *(const float4*)Bptr;
        *(float4*)&Bs[0][brow][bcol] = bv;
    }
    __syncthreads();

    int cur = 0;
    for (int k0 = 0; k0 < K; k0 += 16) {
        float4 av, bv;
        bool have_next = (k0 + 16 < K);
        if (have_next) {
            av = *(const float4*)(Aptr + k0 + 16);
            bv = make_float4(0.f, 0.f, 0.f, 0.f);
            if (bok) bv = *(const float4*)(Bptr + (size_t)(k0 + 16) * N);
        }
        #pragma unroll
        for (int kk = 0; kk < 16; kk++) {
            float a[4], b[4];
            *(float4*)a = *(const float4*)&As[cur][kk][ty * 4];
            *(float4*)b = *(const float4*)&Bs[cur][kk][tx * 4];
            #pragma unroll
            for (int i = 0; i < 4; i++)
                #pragma unroll
                for (int j = 0; j < 4; j++)
                    acc[i][j] += a[i] * b[j];
        }
        if (have_next) {
            int nxt = cur ^ 1;
            As[nxt][aseg + 0][arow] = av.x;
            As[nxt][aseg + 1][arow] = av.y;
            As[nxt][aseg + 2][arow] = av.z;
            As[nxt][aseg + 3][arow] = av.w;
            *(float4*)&Bs[nxt][brow][bcol] = bv;
            __syncthreads();
            cur = nxt;
        }
    }

    int col0 = n0 + tx * 4;
    if (col0 < N) {
        float4 bv4 = make_float4(0.f, 0.f, 0.f, 0.f);
        if (bias) bv4 = *(const float4*)&bias[col0];
        #pragma unroll
        for (int i = 0; i < 4; i++) {
            int row = m0 + ty * 4 + i;
            float4 v = make_float4(acc[i][0] + bv4.x, acc[i][1] + bv4.y,
                                   acc[i][2] + bv4.z, acc[i][3] + bv4.w);
            if (act == 1) {
                v.x = geluf(v.x); v.y = geluf(v.y);
                v.z = geluf(v.z); v.w = geluf(v.w);
            }
            if (resid) {
                float4 r = *(const float4*)&resid[(size_t)row * N + col0];
                v.x += r.x; v.y += r.y; v.z += r.z; v.w += r.w;
            }
            *(float4*)&C[(size_t)row * N + col0] = v;
        }
    }
}

// ---------------- fused dual GEMM: C0 = A@B0, C1 = A@B1 (shared A tile) ----------------
// 64x64 tile, 4x4x2 per thread, double-buffered. M%64==0, N%64==0, K%16==0.
__global__ void gemm2_kernel(const float* __restrict__ A,
                             const float* __restrict__ B0, const float* __restrict__ B1,
                             float* __restrict__ C0, float* __restrict__ C1,
                             int M, int N, int K) {
    __shared__ float As [2][16][64];
    __shared__ float Bs0[2][16][64];
    __shared__ float Bs1[2][16][64];
    int tid = threadIdx.x;            // 256
    int tx = tid & 15, ty = tid >> 4; // 16x16
    int n0 = blockIdx.x * 64;
    int m0 = blockIdx.y * 64;

    float acc0[4][4] = {};
    float acc1[4][4] = {};

    int arow = tid >> 2;              // 0..63
    int aseg = (tid & 3) * 4;         // 0,4,8,12
    int brow = tid >> 4;              // 0..15
    int bcol = (tid & 15) * 4;        // 0..60

    const float* Aptr  = &A [(size_t)(m0 + arow) * K + aseg];
    const float* Bptr0 = &B0[(size_t)brow * N + n0 + bcol];
    const float* Bptr1 = &B1[(size_t)brow * N + n0 + bcol];

    // preload tile 0
    {
        float4 av = *(const float4*)Aptr;
        As[0][aseg + 0][arow] = av.x;
        As[0][aseg + 1][arow] = av.y;
        As[0][aseg + 2][arow] = av.z;
        As[0][aseg + 3][arow] = av.w;
        *(float4*)&Bs0[0][brow][bcol] = *(const float4*)Bptr0;
        *(float4*)&Bs1[0][brow][bcol] = *(const float4*)Bptr1;
    }
    __syncthreads();

    int cur = 0;
    for (int k0 = 0; k0 < K; k0 += 16) {
        float4 av, bv0, bv1;
        bool have_next = (k0 + 16 < K);
        if (have_next) {
            av  = *(const float4*)(Aptr  + k0 + 16);
            bv0 = *(const float4*)(Bptr0 + (size_t)(k0 + 16) * N);
            bv1 = *(const float4*)(Bptr1 + (size_t)(k0 + 16) * N);
        }
        #pragma unroll
        for (int kk = 0; kk < 16; kk++) {
            float a[4], b0[4], b1[4];
            *(float4*)a  = *(const float4*)&As [cur][kk][ty * 4];
            *(float4*)b0 = *(const float4*)&Bs0[cur][kk][tx * 4];
            *(float4*)b1 = *(const float4*)&Bs1[cur][kk][tx * 4];
            #pragma unroll
            for (int i = 0; i < 4; i++)
                #pragma unroll
                for (int j = 0; j < 4; j++) {
                    acc0[i][j] += a[i] * b0[j];
                    acc1[i][j] += a[i] * b1[j];
                }
        }
        if (have_next) {
            int nxt = cur ^ 1;
            As[nxt][aseg + 0][arow] = av.x;
            As[nxt][aseg + 1][arow] = av.y;
            As[nxt][aseg + 2][arow] = av.z;
            As[nxt][aseg + 3][arow] = av.w;
            *(float4*)&Bs0[nxt][brow][bcol] = bv0;
            *(float4*)&Bs1[nxt][brow][bcol] = bv1;
            __syncthreads();
            cur = nxt;
        }
    }

    int col0 = n0 + tx * 4;
    #pragma unroll
    for (int i = 0; i < 4; i++) {
        int row = m0 + ty * 4 + i;
        float4 v0 = make_float4(acc0[i][0], acc0[i][1], acc0[i][2], acc0[i][3]);
        float4 v1 = make_float4(acc1[i][0], acc1[i][1], acc1[i][2], acc1[i][3]);
        *(float4*)&C0[(size_t)row * N + col0] = v0;
        *(float4*)&C1[(size_t)row * N + col0] = v1;
    }
}

// ---------------- 3xTF32 tensor-core GEMM, 128x128x16 tile ----------------
// C = act(A@B + bias). A [M,K] row-major, B [K,N] row-major.
// M%128==0, K%16==0, N%4==0 (N even for float2 epilogue).
// 8 warps, each computes a 64x32 warp tile via mma.m16n8k8 tf32.
// Each fp32 operand split hi+lo; D += Ahi*Bhi + Ahi*Blo + Alo*Bhi (~fp32 accuracy).
__global__ void __launch_bounds__(256)
tfgemm_kernel(const float* __restrict__ A, const float* __restrict__ Bm,
              const float* __restrict__ bias, float* __restrict__ C,
              int M, int N, int K, int act) {
    __shared__ float As[2][16][136];   // [k][m], stride 136 -> conflict-free frag loads
    __shared__ float Bs[2][16][136];   // [k][n]
    int tid = threadIdx.x;
    int lane = tid & 31;
    int wid  = tid >> 5;
    int g  = lane >> 2;      // 0..7
    int tg = lane & 3;       // 0..3
    int mw = (wid >> 2) * 64;   // 0 or 64
    int nw = (wid & 3) * 32;    // 0,32,64,96
    int m0 = blockIdx.y * 128, n0 = blockIdx.x * 128;

    float acc[4][4][4];
    #pragma unroll
    for (int f = 0; f < 4; f++)
        #pragma unroll
        for (int h = 0; h < 4; h++)
            #pragma unroll
            for (int j = 0; j < 4; j++) acc[f][h][j] = 0.f;

    int arow = tid >> 1;          // 0..127
    int akk  = (tid & 1) * 8;     // 0 or 8
    int bkk  = tid >> 4;          // 0..15
    int bnn  = (tid & 15) * 8;    // 0..120
    const float* Aptr = &A[(size_t)(m0 + arow) * K + akk];
    const float* Bptr = &Bm[(size_t)bkk * N + n0 + bnn];
    bool bok0 = (n0 + bnn)     < N;
    bool bok1 = (n0 + bnn + 4) < N;

    // preload tile 0
    {
        float4 a0 = *(const float4*)(Aptr + 0);
        float4 a1 = *(const float4*)(Aptr + 4);
        As[0][akk + 0][arow] = a0.x; As[0][akk + 1][arow] = a0.y;
        As[0][akk + 2][arow] = a0.z; As[0][akk + 3][arow] = a0.w;
        As[0][akk + 4][arow] = a1.x; As[0][akk + 5][arow] = a1.y;
        As[0][akk + 6][arow] = a1.z; As[0][akk + 7][arow] = a1.w;
        float4 b0 = make_float4(0.f, 0.f, 0.f, 0.f);
        float4 b1 = make_float4(0.f, 0.f, 0.f, 0.f);
        if (bok0) b0 = *(const float4*)(Bptr);
        if (bok1) b1 = *(const float4*)(Bptr + 4);
        *(float4*)&Bs[0][bkk][bnn]     = b0;
        *(float4*)&Bs[0][bkk][bnn + 4] = b1;
    }
    __syncthreads();

    int cur = 0;
    for (int k0 = 0; k0 < K; k0 += 16) {
        float4 pa0, pa1, pb0, pb1;
        bool have_next = (k0 + 16 < K);
        if (have_next) {
            pa0 = *(const float4*)(Aptr + k0 + 16);
            pa1 = *(const float4*)(Aptr + k0 + 20);
            pb0 = make_float4(0.f, 0.f, 0.f, 0.f);
            pb1 = make_float4(0.f, 0.f, 0.f, 0.f);
            if (bok0) pb0 = *(const float4*)(Bptr + (size_t)(k0 + 16) * N);
            if (bok1) pb1 = *(const float4*)(Bptr + (size_t)(k0 + 16) * N + 4);
        }

        #pragma unroll
        for (int ks = 0; ks < 2; ks++) {
            int kk = ks * 8;
            // B fragments: b0 = B[k=tg][n], b1 = B[k=tg+4][n]
            uint32_t bhi[4][2], blo[4][2];
            #pragma unroll
            for (int h = 0; h < 4; h++) {
                int n = nw + h * 8 + g;
                tf32_split(Bs[cur][kk + tg    ][n], bhi[h][0], blo[h][0]);
                tf32_split(Bs[cur][kk + tg + 4][n], bhi[h][1], blo[h][1]);
            }
            #pragma unroll
            for (int f = 0; f < 4; f++) {
                int m = mw + f * 16 + g;
                // A fragment: a0=(g,tg) a1=(g+8,tg) a2=(g,tg+4) a3=(g+8,tg+4)
                uint32_t ahi[4], alo[4];
                tf32_split(As[cur][kk + tg    ][m    ], ahi[0], alo[0]);
                tf32_split(As[cur][kk + tg    ][m + 8], ahi[1], alo[1]);
                tf32_split(As[cur][kk + tg + 4][m    ], ahi[2], alo[2]);
                tf32_split(As[cur][kk + tg + 4][m + 8], ahi[3], alo[3]);
                #pragma unroll
                for (int h = 0; h < 4; h++) {
                    mma_tf32(acc[f][h], ahi, blo[h]);
                    mma_tf32(acc[f][h], alo, bhi[h]);
                    mma_tf32(acc[f][h], ahi, bhi[h]);
                }
            }
        }

        if (have_next) {
            int nb = cur ^ 1;
            As[nb][akk + 0][arow] = pa0.x; As[nb][akk + 1][arow] = pa0.y;
            As[nb][akk + 2][arow] = pa0.z; As[nb][akk + 3][arow] = pa0.w;
            As[nb][akk + 4][arow] = pa1.x; As[nb][akk + 5][arow] = pa1.y;
            As[nb][akk + 6][arow] = pa1.z; As[nb][akk + 7][arow] = pa1.w;
            *(float4*)&Bs[nb][bkk][bnn]     = pb0;
            *(float4*)&Bs[nb][bkk][bnn + 4] = pb1;
            __syncthreads();
            cur = nb;
        }
    }

    // epilogue: c0=(g, tg*2) c1=(g, tg*2+1) c2=(g+8, tg*2) c3=(g+8, tg*2+1)
    #pragma unroll
    for (int h = 0; h < 4; h++) {
        int col = n0 + nw + h * 8 + tg * 2;
        if (col >= N) continue;
        float2 bv = make_float2(0.f, 0.f);
        if (bias) bv = *(const float2*)&bias[col];
        #pragma unroll
        for (int f = 0; f < 4; f++) {
            int row = m0 + mw + f * 16 + g;
            float2 v0 = make_float2(acc[f][h][0] + bv.x, acc[f][h][1] + bv.y);
            float2 v1 = make_float2(acc[f][h][2] + bv.x, acc[f][h][3] + bv.y);
            if (act == 1) {
                v0.x = geluf(v0.x); v0.y = geluf(v0.y);
                v1.x = geluf(v1.x); v1.y = geluf(v1.y);
            }
            *(float2*)&C[(size_t)row * N + col]       = v0;
            *(float2*)&C[(size_t)(row + 8) * N + col] = v1;
        }
    }
}

// ---------------- dt = softplus(p[:, :32] @ dt_w + dt_b) ----------------
__global__ void dt_kernel(const float* __restrict__ dt_w, const float* __restrict__ dt_b) {
    int row = blockIdx.x;   // ROWS
    int e = threadIdx.x;    // 512
    const float* pr = &g_p[row * PDIM];
    float acc = dt_b[e];
    #pragma unroll
    for (int r = 0; r < DTRN; r++)
        acc += pr[r] * dt_w[r * EMBEDD + e];
    g_dt[row * EMBEDD + e] = softplusf(acc);
}

// ---------------- depthwise causal conv (DCONV=4) + silu ----------------
__global__ void conv_kernel(const float* __restrict__ cw) {
    int row = blockIdx.x;
    int e = threadIdx.x;
    int b = row / LSEQ, l = row % LSEQ;
    float acc = 0.f;
    #pragma unroll
    for (int k = 0; k < DCONVN; k++) {
        int lsrc = l - (DCONVN - 1) + k;
        if (lsrc >= 0)
            acc += g_xp[(b * LSEQ + lsrc) * EMBEDD + e] * cw[e * DCONVN + k];
    }
    g_u[row * EMBEDD + e] = siluf(acc);
}

// ---------------- SSM scan with shared-memory staging ----------------
#define TCHUNK 64
__global__ void __launch_bounds__(128)
scan_kernel(const float* __restrict__ A_log, const float* __restrict__ Dparam) {
    __shared__ float sB [TCHUNK][NSTATE];   // 4KB
    __shared__ float sC [TCHUNK][NSTATE];   // 4KB
    __shared__ float sdt[TCHUNK][8];        // 2KB
    __shared__ float su [TCHUNK][8];        // 2KB

    int tid  = threadIdx.x;
    int n    = tid & 15;        // state index
    int dloc = tid >> 4;        // 0..7
    int b    = blockIdx.x / (EMBEDD / 8);
    int d0   = (blockIdx.x % (EMBEDD / 8)) * 8;
    int d    = d0 + dloc;

    float A = -expf(A_log[d * NSTATE + n]);
    float Ainv = 1.0f / (A + 1e-8f);
    float Dp = Dparam[d];
    float h = 0.0f;

    for (int t0 = 0; t0 < LSEQ; t0 += TCHUNK) {
        __syncthreads();  // protect previous chunk's smem from overwrite
        #pragma unroll
        for (int idx = tid; idx < TCHUNK * NSTATE; idx += 128) {
            int tt = idx >> 4, nn = idx & 15;
            int rowi = b * LSEQ + t0 + tt;
            sB[tt][nn] = g_p[rowi * PDIM + DTRN + nn];
            sC[tt][nn] = g_p[rowi * PDIM + DTRN + NSTATE + nn];
        }
        #pragma unroll
        for (int idx = tid; idx < TCHUNK * 8; idx += 128) {
            int tt = idx >> 3, dl = idx & 7;
            int rowi = b * LSEQ + t0 + tt;
            sdt[tt][dl] = g_dt[rowi * EMBEDD + d0 + dl];
            su [tt][dl] = g_u [rowi * EMBEDD + d0 + dl];
        }
        __syncthreads();

        for (int tt = 0; tt < TCHUNK; tt++) {
            float dtv = sdt[tt][dloc];
            float uv  = su [tt][dloc];
            float Bp  = sB [tt][n];
            float Cp  = sC [tt][n];
            float At = expf(A * dtv);
            float Bt = (At - 1.0f) * Ainv;
            h = At * h + Bt * Bp * uv;
            float c = Cp * h;
            c += __shfl_xor_sync(0xffffffffu, c, 8, 16);
            c += __shfl_xor_sync(0xffffffffu, c, 4, 16);
            c += __shfl_xor_sync(0xffffffffu, c, 2, 16);
            c += __shfl_xor_sync(0xffffffffu, c, 1, 16);
            if (n == 0) {
                int rowi = b * LSEQ + t0 + tt;
                float yv = c + uv * Dp;
                float zv = g_z[rowi * EMBEDD + d];
                g_y[rowi * EMBEDD + d] = yv * siluf(zv);
            }
        }
    }
}

// ---------------- host launcher ----------------
extern "C" void kernel_launch(void* const* d_in, const int* in_sizes, int n_in,
                              void* d_out, int out_size) {
    const int*   tokens  = (const int*)  d_in[0];
    const int*   t       = (const int*)  d_in[1];
    const float* tok_emb = (const float*)d_in[2];
    const float* time_w1 = (const float*)d_in[3];
    const float* time_b1 = (const float*)d_in[4];
    const float* time_w2 = (const float*)d_in[5];
    const float* time_b2 = (const float*)d_in[6];
    const float* n1_s    = (const float*)d_in[7];
    const float* n1_b    = (const float*)d_in[8];
    const float* wx      = (const float*)d_in[9];
    const float* wz      = (const float*)d_in[10];
    const float* wp      = (const float*)d_in[11];
    const float* conv_w  = (const float*)d_in[12];
    const float* dt_w    = (const float*)d_in[13];
    const float* dt_b    = (const float*)d_in[14];
    const float* A_log   = (const float*)d_in[15];
    const float* Dparam  = (const float*)d_in[16];
    const float* wo      = (const float*)d_in[17];
    const float* n2_s    = (const float*)d_in[18];
    const float* n2_b    = (const float*)d_in[19];
    const float* mlp_w1  = (const float*)d_in[20];
    const float* mlp_b1  = (const float*)d_in[21];
    const float* mlp_w2  = (const float*)d_in[22];
    const float* mlp_b2  = (const float*)d_in[23];
    const float* no_s    = (const float*)d_in[24];
    const float* no_b    = (const float*)d_in[25];
    const float* head_w  = (const float*)d_in[26];
    const float* head_b  = (const float*)d_in[27];
    float* out = (float*)d_out;

    float *px, *ph, *pxp, *pz, *pp, *py, *pmlp;
    cudaGetSymbolAddress((void**)&px,   g_x);
    cudaGetSymbolAddress((void**)&ph,   g_h);
    cudaGetSymbolAddress((void**)&pxp,  g_xp);
    cudaGetSymbolAddress((void**)&pz,   g_z);
    cudaGetSymbolAddress((void**)&pp,   g_p);
    cudaGetSymbolAddress((void**)&py,   g_y);
    cudaGetSymbolAddress((void**)&pmlp, g_mlp);

    // time embedding + token embedding
    time_feat_kernel<<<1, EMBEDD>>>(t);
    time_mlp1_kernel<<<(BBATCH * MLPDIM + 255) / 256, 256>>>(time_w1, time_b1);
    time_mlp2_kernel<<<(BBATCH * EMBEDD + 255) / 256, 256>>>(time_w2, time_b2);
    embed_kernel<<<ROWS, EMBEDD>>>(tokens, tok_emb);

    dim3 gE((EMBEDD + 63) / 64, ROWS / 64);       // 64-tile, N=512  (grid 8x32)
    dim3 gP((PDIM   + 63) / 64, ROWS / 64);       // 64-tile, N=64   (grid 1x32)
    dim3 gM((MLPDIM + 127) / 128, ROWS / 128);    // 128-tile, N=2048 (grid 16x16)
    dim3 gV((VOCABN + 127) / 128, ROWS / 128);    // 128-tile, N=50000 (grid 391x16)

    for (int i = 0; i < DEPTHN; i++) {
        // ln1
        ln_kernel<<<ROWS, EMBEDD>>>(px, ph, n1_s + i * EMBEDD, n1_b + i * EMBEDD);
        // fused xp/z projections (shared A tiles)
        gemm2_kernel<<<gE, 256>>>(ph, wx + (size_t)i * EMBEDD * EMBEDD,
                                      wz + (size_t)i * EMBEDD * EMBEDD,
                                      pxp, pz, ROWS, EMBEDD, EMBEDD);
        // p projection
        gemm_kernel<<<gP, 256>>>(ph, wp + (size_t)i * EMBEDD * PDIM,   nullptr, nullptr, pp,  ROWS, PDIM,   EMBEDD, 0);
        // dt projection + softplus
        dt_kernel<<<ROWS, EMBEDD>>>(dt_w + (size_t)i * DTRN * EMBEDD, dt_b + i * EMBEDD);
        // causal depthwise conv + silu
        conv_kernel<<<ROWS, EMBEDD>>>(conv_w + (size_t)i * EMBEDD * DCONVN);
        // selective scan + gate (smem-staged)
        scan_kernel<<<BBATCH * (EMBEDD / 8), 128>>>(A_log + (size_t)i * EMBEDD * NSTATE,
                                                    Dparam + i * EMBEDD);
        // out projection + residual (x = x + y @ wo)
        gemm_kernel<<<gE, 256>>>(py, wo + (size_t)i * EMBEDD * EMBEDD, nullptr, px, px, ROWS, EMBEDD, EMBEDD, 0);
        // ln2 + MLP
        ln_kernel<<<ROWS, EMBEDD>>>(px, ph, n2_s + i * EMBEDD, n2_b + i * EMBEDD);
        tfgemm_kernel<<<gM, 256>>>(ph, mlp_w1 + (size_t)i * EMBEDD * MLPDIM, mlp_b1 + i * MLPDIM, pmlp, ROWS, MLPDIM, EMBEDD, 1);
        gemm_kernel<<<gE, 256>>>(pmlp, mlp_w2 + (size_t)i * MLPDIM * EMBEDD, mlp_b2 + i * EMBEDD, px, px, ROWS, EMBEDD, MLPDIM, 0);
    }

    // final LN + vocab head (3xTF32 tensor GEMM)
    ln_kernel<<<ROWS, EMBEDD>>>(px, ph, no_s, no_b);
    tfgemm_kernel<<<gV, 256>>>(ph, head_w, head_b, out, ROWS, VOCABN, EMBEDD, 0);
}

// round 16
// speedup vs baseline: 1.0940x; 1.0767x over previous
#include <cuda_runtime.h>
#include <math.h>
#include <stdint.h>

// ---------------- problem constants ----------------
#define EMBEDD 512
#define DEPTHN 6
#define NSTATE 16
#define DCONVN 4
#define DTRN   32
#define VOCABN 50000
#define BBATCH 2
#define LSEQ   1024
#define MLPDIM 2048
#define ROWS   (BBATCH * LSEQ)      // 2048
#define PDIM   (DTRN + 2 * NSTATE)  // 64

// ---------------- scratch (static device, no allocs) ----------------
__device__ float g_x   [ROWS * EMBEDD];
__device__ float g_h   [ROWS * EMBEDD];
__device__ float g_xp  [ROWS * EMBEDD];
__device__ float g_z   [ROWS * EMBEDD];
__device__ float g_p   [ROWS * PDIM];
__device__ float g_dt  [ROWS * EMBEDD];
__device__ float g_u   [ROWS * EMBEDD];
__device__ float g_y   [ROWS * EMBEDD];
__device__ float g_mlp [ROWS * MLPDIM];
__device__ float g_feat[BBATCH * EMBEDD];
__device__ float g_h1  [BBATCH * MLPDIM];
__device__ float g_te  [BBATCH * EMBEDD];

// ---------------- helpers ----------------
__device__ __forceinline__ float siluf(float x) {
    return x / (1.0f + expf(-x));
}
__device__ __forceinline__ float geluf(float x) {
    return 0.5f * x * (1.0f + erff(x * 0.70710678118654752f));
}
__device__ __forceinline__ float softplusf(float x) {
    return fmaxf(x, 0.0f) + log1pf(expf(-fabsf(x)));
}

// Split (v0,v1) into packed bf16x2 hi and lo planes: v = hi + lo.
// Low 16 bits of the packed word hold v0 (the even/earlier k element).
__device__ __forceinline__ void bf16x3_pack(float v0, float v1, uint32_t& hi, uint32_t& lo) {
    uint32_t h;
    asm("cvt.rn.bf16x2.f32 %0, %1, %2;" : "=r"(h) : "f"(v1), "f"(v0));
    float r0 = v0 - __uint_as_float(h << 16);
    float r1 = v1 - __uint_as_float(h & 0xffff0000u);
    asm("cvt.rn.bf16x2.f32 %0, %1, %2;" : "=r"(lo) : "f"(r1), "f"(r0));
    hi = h;
}

__device__ __forceinline__ void mma_bf16(float* d, const uint32_t* a, const uint32_t* b) {
    asm volatile(
        "mma.sync.aligned.m16n8k16.row.col.f32.bf16.bf16.f32 "
        "{%0,%1,%2,%3}, {%4,%5,%6,%7}, {%8,%9}, {%0,%1,%2,%3};\n"
        : "+f"(d[0]), "+f"(d[1]), "+f"(d[2]), "+f"(d[3])
        : "r"(a[0]), "r"(a[1]), "r"(a[2]), "r"(a[3]),
          "r"(b[0]), "r"(b[1]));
}

// ---------------- time embedding ----------------
__global__ void time_feat_kernel(const int* __restrict__ t) {
    int e = threadIdx.x;  // 512
    const int half = EMBEDD / 2;
    int j = (e < half) ? e : (e - half);
    float freq = expf((float)j * (-logf(10000.0f) / (float)(half - 1)));
    for (int b = 0; b < BBATCH; b++) {
        float a = (float)t[b] * freq;
        g_feat[b * EMBEDD + e] = (e < half) ? sinf(a) : cosf(a);
    }
}

__global__ void time_mlp1_kernel(const float* __restrict__ w1, const float* __restrict__ b1) {
    int gid = blockIdx.x * blockDim.x + threadIdx.x;  // BBATCH*MLPDIM
    if (gid >= BBATCH * MLPDIM) return;
    int b = gid / MLPDIM;
    int o = gid % MLPDIM;
    float acc = b1[o];
    #pragma unroll 8
    for (int k = 0; k < EMBEDD; k++)
        acc += g_feat[b * EMBEDD + k] * w1[k * MLPDIM + o];
    g_h1[gid] = siluf(acc);
}

__global__ void time_mlp2_kernel(const float* __restrict__ w2, const float* __restrict__ b2) {
    int gid = blockIdx.x * blockDim.x + threadIdx.x;  // BBATCH*EMBEDD
    if (gid >= BBATCH * EMBEDD) return;
    int b = gid / EMBEDD;
    int e = gid % EMBEDD;
    float acc = b2[e];
    #pragma unroll 8
    for (int k = 0; k < MLPDIM; k++)
        acc += g_h1[b * MLPDIM + k] * w2[k * EMBEDD + e];
    g_te[gid] = acc;
}

// ---------------- embedding ----------------
__global__ void embed_kernel(const int* __restrict__ tokens, const float* __restrict__ emb) {
    int row = blockIdx.x;     // ROWS
    int e   = threadIdx.x;    // 512
    int b   = row / LSEQ;
    int tok = tokens[row];
    g_x[row * EMBEDD + e] = emb[tok * EMBEDD + e] + g_te[b * EMBEDD + e];
}

// ---------------- layernorm (one block per row, 512 threads) ----------------
__global__ void ln_kernel(const float* __restrict__ in, float* __restrict__ out,
                          const float* __restrict__ s, const float* __restrict__ bia) {
    int row = blockIdx.x;
    int e = threadIdx.x;
    float v = in[row * EMBEDD + e];
    float sum = v, sq = v * v;
    #pragma unroll
    for (int m = 16; m; m >>= 1) {
        sum += __shfl_xor_sync(0xffffffffu, sum, m);
        sq  += __shfl_xor_sync(0xffffffffu, sq, m);
    }
    __shared__ float s1[16], s2[16];
    __shared__ float mv, rv;
    int wid = e >> 5, lane = e & 31;
    if (lane == 0) { s1[wid] = sum; s2[wid] = sq; }
    __syncthreads();
    if (e == 0) {
        float ts = 0.f, tq = 0.f;
        #pragma unroll
        for (int i = 0; i < 16; i++) { ts += s1[i]; tq += s2[i]; }
        float m = ts / (float)EMBEDD;
        float var = tq / (float)EMBEDD - m * m;
        mv = m;
        rv = rsqrtf(var + 1e-5f);
    }
    __syncthreads();
    out[row * EMBEDD + e] = (v - mv) * rv * s[e] + bia[e];
}

// ---------------- fp32 SIMT GEMM, 64x64 tile, 4x4/thread, double-buffered ----------------
// C = act(A@B + bias) + resid.  M%64==0, K%16==0, N%4==0. act: 0 none, 1 gelu
__global__ void gemm_kernel(const float* __restrict__ A, const float* __restrict__ Bm,
                            const float* __restrict__ bias, const float* __restrict__ resid,
                            float* __restrict__ C, int M, int N, int K, int act) {
    __shared__ float As[2][16][64];
    __shared__ float Bs[2][16][64];
    int tid = threadIdx.x;            // 256
    int tx = tid & 15, ty = tid >> 4; // 16x16
    int n0 = blockIdx.x * 64;
    int m0 = blockIdx.y * 64;

    float acc[4][4] = {};

    int arow = tid >> 2;              // 0..63
    int aseg = (tid & 3) * 4;         // 0,4,8,12
    int brow = tid >> 4;              // 0..15
    int bcol = (tid & 15) * 4;        // 0..60

    const float* Aptr = &A[(size_t)(m0 + arow) * K + aseg];
    const float* Bptr = &Bm[(size_t)brow * N + n0 + bcol];
    bool bok = (n0 + bcol < N);

    // preload tile 0
    {
        float4 av = *(const float4*)Aptr;
        As[0][aseg + 0][arow] = av.x;
        As[0][aseg + 1][arow] = av.y;
        As[0][aseg + 2][arow] = av.z;
        As[0][aseg + 3][arow] = av.w;
        float4 bv = make_float4(0.f, 0.f, 0.f, 0.f);
        if (bok) bv = *(const float4*)Bptr;
        *(float4*)&Bs[0][brow][bcol] = bv;
    }
    __syncthreads();

    int cur = 0;
    for (int k0 = 0; k0 < K; k0 += 16) {
        float4 av, bv;
        bool have_next = (k0 + 16 < K);
        if (have_next) {
            av = *(const float4*)(Aptr + k0 + 16);
            bv = make_float4(0.f, 0.f, 0.f, 0.f);
            if (bok) bv = *(const float4*)(Bptr + (size_t)(k0 + 16) * N);
        }
        #pragma unroll
        for (int kk = 0; kk < 16; kk++) {
            float a[4], b[4];
            *(float4*)a = *(const float4*)&As[cur][kk][ty * 4];
            *(float4*)b = *(const float4*)&Bs[cur][kk][tx * 4];
            #pragma unroll
            for (int i = 0; i < 4; i++)
                #pragma unroll
                for (int j = 0; j < 4; j++)
                    acc[i][j] += a[i] * b[j];
        }
        if (have_next) {
            int nxt = cur ^ 1;
            As[nxt][aseg + 0][arow] = av.x;
            As[nxt][aseg + 1][arow] = av.y;
            As[nxt][aseg + 2][arow] = av.z;
            As[nxt][aseg + 3][arow] = av.w;
            *(float4*)&Bs[nxt][brow][bcol] = bv;
            __syncthreads();
            cur = nxt;
        }
    }

    int col0 = n0 + tx * 4;
    if (col0 < N) {
        float4 bv4 = make_float4(0.f, 0.f, 0.f, 0.f);
        if (bias) bv4 = *(const float4*)&bias[col0];
        #pragma unroll
        for (int i = 0; i < 4; i++) {
            int row = m0 + ty * 4 + i;
            float4 v = make_float4(acc[i][0] + bv4.x, acc[i][1] + bv4.y,
                                   acc[i][2] + bv4.z, acc[i][3] + bv4.w);
            if (act == 1) {
                v.x = geluf(v.x); v.y = geluf(v.y);
                v.z = geluf(v.z); v.w = geluf(v.w);
            }
            if (resid) {
                float4 r = *(const float4*)&resid[(size_t)row * N + col0];
                v.x += r.x; v.y += r.y; v.z += r.z; v.w += r.w;
            }
            *(float4*)&C[(size_t)row * N + col0] = v;
        }
    }
}

// ---------------- fused dual GEMM: C0 = A@B0, C1 = A@B1 (shared A tile) ----------------
// 64x64 tile, 4x4x2 per thread, double-buffered. M%64==0, N%64==0, K%16==0.
__global__ void gemm2_kernel(const float* __restrict__ A,
                             const float* __restrict__ B0, const float* __restrict__ B1,
                             float* __restrict__ C0, float* __restrict__ C1,
                             int M, int N, int K) {
    __shared__ float As [2][16][64];
    __shared__ float Bs0[2][16][64];
    __shared__ float Bs1[2][16][64];
    int tid = threadIdx.x;            // 256
    int tx = tid & 15, ty = tid >> 4; // 16x16
    int n0 = blockIdx.x * 64;
    int m0 = blockIdx.y * 64;

    float acc0[4][4] = {};
    float acc1[4][4] = {};

    int arow = tid >> 2;              // 0..63
    int aseg = (tid & 3) * 4;         // 0,4,8,12
    int brow = tid >> 4;              // 0..15
    int bcol = (tid & 15) * 4;        // 0..60

    const float* Aptr  = &A [(size_t)(m0 + arow) * K + aseg];
    const float* Bptr0 = &B0[(size_t)brow * N + n0 + bcol];
    const float* Bptr1 = &B1[(size_t)brow * N + n0 + bcol];

    // preload tile 0
    {
        float4 av = *(const float4*)Aptr;
        As[0][aseg + 0][arow] = av.x;
        As[0][aseg + 1][arow] = av.y;
        As[0][aseg + 2][arow] = av.z;
        As[0][aseg + 3][arow] = av.w;
        *(float4*)&Bs0[0][brow][bcol] = *(const float4*)Bptr0;
        *(float4*)&Bs1[0][brow][bcol] = *(const float4*)Bptr1;
    }
    __syncthreads();

    int cur = 0;
    for (int k0 = 0; k0 < K; k0 += 16) {
        float4 av, bv0, bv1;
        bool have_next = (k0 + 16 < K);
        if (have_next) {
            av  = *(const float4*)(Aptr  + k0 + 16);
            bv0 = *(const float4*)(Bptr0 + (size_t)(k0 + 16) * N);
            bv1 = *(const float4*)(Bptr1 + (size_t)(k0 + 16) * N);
        }
        #pragma unroll
        for (int kk = 0; kk < 16; kk++) {
            float a[4], b0[4], b1[4];
            *(float4*)a  = *(const float4*)&As [cur][kk][ty * 4];
            *(float4*)b0 = *(const float4*)&Bs0[cur][kk][tx * 4];
            *(float4*)b1 = *(const float4*)&Bs1[cur][kk][tx * 4];
            #pragma unroll
            for (int i = 0; i < 4; i++)
                #pragma unroll
                for (int j = 0; j < 4; j++) {
                    acc0[i][j] += a[i] * b0[j];
                    acc1[i][j] += a[i] * b1[j];
                }
        }
        if (have_next) {
            int nxt = cur ^ 1;
            As[nxt][aseg + 0][arow] = av.x;
            As[nxt][aseg + 1][arow] = av.y;
            As[nxt][aseg + 2][arow] = av.z;
            As[nxt][aseg + 3][arow] = av.w;
            *(float4*)&Bs0[nxt][brow][bcol] = bv0;
            *(float4*)&Bs1[nxt][brow][bcol] = bv1;
            __syncthreads();
            cur = nxt;
        }
    }

    int col0 = n0 + tx * 4;
    #pragma unroll
    for (int i = 0; i < 4; i++) {
        int row = m0 + ty * 4 + i;
        float4 v0 = make_float4(acc0[i][0], acc0[i][1], acc0[i][2], acc0[i][3]);
        float4 v1 = make_float4(acc1[i][0], acc1[i][1], acc1[i][2], acc1[i][3]);
        *(float4*)&C0[(size_t)row * N + col0] = v0;
        *(float4*)&C1[(size_t)row * N + col0] = v1;
    }
}

// ---------------- 3xBF16 tensor-core GEMM, 128x128x32 tile ----------------
// C = act(A@B + bias). A [M,K] row-major, B [K,N] row-major.
// M%128==0, K%32==0, N%4==0. 8 warps, 64x32 warp tile, mma.m16n8k16.bf16.
// fp32 operands split at smem-store time into bf16 hi+lo planes (packed bf16x2
// along k); D += Ahi*Bhi + Ahi*Blo + Alo*Bhi (drops lo*lo ~ 1.5e-5 relative).
__global__ void __launch_bounds__(256)
bfgemm_kernel(const float* __restrict__ A, const float* __restrict__ Bm,
              const float* __restrict__ bias, float* __restrict__ C,
              int M, int N, int K, int act) {
    // [k-pair][row/col], stride 132 -> conflict-free fragment gathers
    __shared__ uint32_t Ah[16][132], Al[16][132];
    __shared__ uint32_t Bh[16][132], Bl[16][132];

    int tid = threadIdx.x;
    int lane = tid & 31;
    int wid  = tid >> 5;
    int g  = lane >> 2;        // 0..7
    int tg = lane & 3;         // 0..3
    int mw = (wid >> 2) * 64;  // 0 or 64
    int nw = (wid & 3) * 32;   // 0,32,64,96
    int m0 = blockIdx.y * 128, n0 = blockIdx.x * 128;

    float acc[4][4][4];
    #pragma unroll
    for (int f = 0; f < 4; f++)
        #pragma unroll
        for (int h = 0; h < 4; h++)
            #pragma unroll
            for (int j = 0; j < 4; j++) acc[f][h][j] = 0.f;

    // A loader: row = tid&127, k-half = (tid>>7)*16 (16 floats per thread)
    int arow = tid & 127;
    int akh  = (tid >> 7) * 16;
    const float* Aptr = &A[(size_t)(m0 + arow) * K + akh];
    // B loader: k-pair kp = tid>>4 (0..15), n-segment = (tid&15)*8
    int bkp = tid >> 4;
    int bns = (tid & 15) * 8;
    const float* Bp0 = &Bm[(size_t)(2 * bkp)     * N + n0 + bns];
    const float* Bp1 = &Bm[(size_t)(2 * bkp + 1) * N + n0 + bns];
    bool ok0 = (n0 + bns)     < N;
    bool ok1 = (n0 + bns + 4) < N;

    const int NCH = K / 32;
    float4 a0, a1, a2, a3, be0, be1, bo0, bo1;

    // prefetch chunk 0
    {
        a0 = *(const float4*)(Aptr + 0);
        a1 = *(const float4*)(Aptr + 4);
        a2 = *(const float4*)(Aptr + 8);
        a3 = *(const float4*)(Aptr + 12);
        be0 = be1 = bo0 = bo1 = make_float4(0.f, 0.f, 0.f, 0.f);
        if (ok0) { be0 = *(const float4*)(Bp0);     bo0 = *(const float4*)(Bp1); }
        if (ok1) { be1 = *(const float4*)(Bp0 + 4); bo1 = *(const float4*)(Bp1 + 4); }
    }

    for (int c = 0; c < NCH; c++) {
        // ---- store prefetched chunk into split smem planes ----
        {
            int kb = (tid >> 7) * 8;  // A k-pair base (0 or 8)
            float av[16] = {a0.x, a0.y, a0.z, a0.w, a1.x, a1.y, a1.z, a1.w,
                            a2.x, a2.y, a2.z, a2.w, a3.x, a3.y, a3.z, a3.w};
            #pragma unroll
            for (int j = 0; j < 8; j++) {
                uint32_t hi, lo;
                bf16x3_pack(av[2 * j], av[2 * j + 1], hi, lo);
                Ah[kb + j][arow] = hi;
                Al[kb + j][arow] = lo;
            }
            float ev[8] = {be0.x, be0.y, be0.z, be0.w, be1.x, be1.y, be1.z, be1.w};
            float ov[8] = {bo0.x, bo0.y, bo0.z, bo0.w, bo1.x, bo1.y, bo1.z, bo1.w};
            #pragma unroll
            for (int j = 0; j < 8; j++) {
                uint32_t hi, lo;
                bf16x3_pack(ev[j], ov[j], hi, lo);  // low half = even k
                Bh[bkp][bns + j] = hi;
                Bl[bkp][bns + j] = lo;
            }
        }
        __syncthreads();

        // ---- prefetch next chunk (latency overlaps MMA below) ----
        if (c + 1 < NCH) {
            int ko = (c + 1) * 32;
            a0 = *(const float4*)(Aptr + ko + 0);
            a1 = *(const float4*)(Aptr + ko + 4);
            a2 = *(const float4*)(Aptr + ko + 8);
            a3 = *(const float4*)(Aptr + ko + 12);
            be0 = be1 = bo0 = bo1 = make_float4(0.f, 0.f, 0.f, 0.f);
            if (ok0) { be0 = *(const float4*)(Bp0 + (size_t)ko * N);     bo0 = *(const float4*)(Bp1 + (size_t)ko * N); }
            if (ok1) { be1 = *(const float4*)(Bp0 + (size_t)ko * N + 4); bo1 = *(const float4*)(Bp1 + (size_t)ko * N + 4); }
        }

        // ---- MMA over the chunk: 2 k16 steps ----
        #pragma unroll
        for (int ks = 0; ks < 2; ks++) {
            int kpb = ks * 8;
            uint32_t bh[4][2], bl[4][2];
            #pragma unroll
            for (int h = 0; h < 4; h++) {
                int n = nw + h * 8 + g;
                bh[h][0] = Bh[kpb + tg    ][n];
                bh[h][1] = Bh[kpb + tg + 4][n];
                bl[h][0] = Bl[kpb + tg    ][n];
                bl[h][1] = Bl[kpb + tg + 4][n];
            }
            #pragma unroll
            for (int f = 0; f < 4; f++) {
                int m = mw + f * 16 + g;
                uint32_t ah[4], al[4];
                ah[0] = Ah[kpb + tg    ][m];
                ah[1] = Ah[kpb + tg    ][m + 8];
                ah[2] = Ah[kpb + tg + 4][m];
                ah[3] = Ah[kpb + tg + 4][m + 8];
                al[0] = Al[kpb + tg    ][m];
                al[1] = Al[kpb + tg    ][m + 8];
                al[2] = Al[kpb + tg + 4][m];
                al[3] = Al[kpb + tg + 4][m + 8];
                #pragma unroll
                for (int h = 0; h < 4; h++) {
                    mma_bf16(acc[f][h], ah, bh[h]);
                    mma_bf16(acc[f][h], ah, bl[h]);
                    mma_bf16(acc[f][h], al, bh[h]);
                }
            }
        }
        __syncthreads();  // MMA done before next chunk's smem stores
    }

    // epilogue: c0=(g, tg*2) c1=(g, tg*2+1) c2=(g+8, tg*2) c3=(g+8, tg*2+1)
    #pragma unroll
    for (int h = 0; h < 4; h++) {
        int col = n0 + nw + h * 8 + tg * 2;
        if (col >= N) continue;
        float2 bv = make_float2(0.f, 0.f);
        if (bias) bv = *(const float2*)&bias[col];
        #pragma unroll
        for (int f = 0; f < 4; f++) {
            int row = m0 + mw + f * 16 + g;
            float2 v0 = make_float2(acc[f][h][0] + bv.x, acc[f][h][1] + bv.y);
            float2 v1 = make_float2(acc[f][h][2] + bv.x, acc[f][h][3] + bv.y);
            if (act == 1) {
                v0.x = geluf(v0.x); v0.y = geluf(v0.y);
                v1.x = geluf(v1.x); v1.y = geluf(v1.y);
            }
            *(float2*)&C[(size_t)row * N + col]       = v0;
            *(float2*)&C[(size_t)(row + 8) * N + col] = v1;
        }
    }
}

// ---------------- dt = softplus(p[:, :32] @ dt_w + dt_b) ----------------
__global__ void dt_kernel(const float* __restrict__ dt_w, const float* __restrict__ dt_b) {
    int row = blockIdx.x;   // ROWS
    int e = threadIdx.x;    // 512
    const float* pr = &g_p[row * PDIM];
    float acc = dt_b[e];
    #pragma unroll
    for (int r = 0; r < DTRN; r++)
        acc += pr[r] * dt_w[r * EMBEDD + e];
    g_dt[row * EMBEDD + e] = softplusf(acc);
}

// ---------------- depthwise causal conv (DCONV=4) + silu ----------------
__global__ void conv_kernel(const float* __restrict__ cw) {
    int row = blockIdx.x;
    int e = threadIdx.x;
    int b = row / LSEQ, l = row % LSEQ;
    float acc = 0.f;
    #pragma unroll
    for (int k = 0; k < DCONVN; k++) {
        int lsrc = l - (DCONVN - 1) + k;
        if (lsrc >= 0)
            acc += g_xp[(b * LSEQ + lsrc) * EMBEDD + e] * cw[e * DCONVN + k];
    }
    g_u[row * EMBEDD + e] = siluf(acc);
}

// ---------------- SSM scan with shared-memory staging ----------------
#define TCHUNK 64
__global__ void __launch_bounds__(128)
scan_kernel(const float* __restrict__ A_log, const float* __restrict__ Dparam) {
    __shared__ float sB [TCHUNK][NSTATE];   // 4KB
    __shared__ float sC [TCHUNK][NSTATE];   // 4KB
    __shared__ float sdt[TCHUNK][8];        // 2KB
    __shared__ float su [TCHUNK][8];        // 2KB

    int tid  = threadIdx.x;
    int n    = tid & 15;        // state index
    int dloc = tid >> 4;        // 0..7
    int b    = blockIdx.x / (EMBEDD / 8);
    int d0   = (blockIdx.x % (EMBEDD / 8)) * 8;
    int d    = d0 + dloc;

    float A = -expf(A_log[d * NSTATE + n]);
    float Ainv = 1.0f / (A + 1e-8f);
    float Dp = Dparam[d];
    float h = 0.0f;

    for (int t0 = 0; t0 < LSEQ; t0 += TCHUNK) {
        __syncthreads();  // protect previous chunk's smem from overwrite
        #pragma unroll
        for (int idx = tid; idx < TCHUNK * NSTATE; idx += 128) {
            int tt = idx >> 4, nn = idx & 15;
            int rowi = b * LSEQ + t0 + tt;
            sB[tt][nn] = g_p[rowi * PDIM + DTRN + nn];
            sC[tt][nn] = g_p[rowi * PDIM + DTRN + NSTATE + nn];
        }
        #pragma unroll
        for (int idx = tid; idx < TCHUNK * 8; idx += 128) {
            int tt = idx >> 3, dl = idx & 7;
            int rowi = b * LSEQ + t0 + tt;
            sdt[tt][dl] = g_dt[rowi * EMBEDD + d0 + dl];
            su [tt][dl] = g_u [rowi * EMBEDD + d0 + dl];
        }
        __syncthreads();

        for (int tt = 0; tt < TCHUNK; tt++) {
            float dtv = sdt[tt][dloc];
            float uv  = su [tt][dloc];
            float Bp  = sB [tt][n];
            float Cp  = sC [tt][n];
            float At = expf(A * dtv);
            float Bt = (At - 1.0f) * Ainv;
            h = At * h + Bt * Bp * uv;
            float c = Cp * h;
            c += __shfl_xor_sync(0xffffffffu, c, 8, 16);
            c += __shfl_xor_sync(0xffffffffu, c, 4, 16);
            c += __shfl_xor_sync(0xffffffffu, c, 2, 16);
            c += __shfl_xor_sync(0xffffffffu, c, 1, 16);
            if (n == 0) {
                int rowi = b * LSEQ + t0 + tt;
                float yv = c + uv * Dp;
                float zv = g_z[rowi * EMBEDD + d];
                g_y[rowi * EMBEDD + d] = yv * siluf(zv);
            }
        }
    }
}

// ---------------- host launcher ----------------
extern "C" void kernel_launch(void* const* d_in, const int* in_sizes, int n_in,
                              void* d_out, int out_size) {
    const int*   tokens  = (const int*)  d_in[0];
    const int*   t       = (const int*)  d_in[1];
    const float* tok_emb = (const float*)d_in[2];
    const float* time_w1 = (const float*)d_in[3];
    const float* time_b1 = (const float*)d_in[4];
    const float* time_w2 = (const float*)d_in[5];
    const float* time_b2 = (const float*)d_in[6];
    const float* n1_s    = (const float*)d_in[7];
    const float* n1_b    = (const float*)d_in[8];
    const float* wx      = (const float*)d_in[9];
    const float* wz      = (const float*)d_in[10];
    const float* wp      = (const float*)d_in[11];
    const float* conv_w  = (const float*)d_in[12];
    const float* dt_w    = (const float*)d_in[13];
    const float* dt_b    = (const float*)d_in[14];
    const float* A_log   = (const float*)d_in[15];
    const float* Dparam  = (const float*)d_in[16];
    const float* wo      = (const float*)d_in[17];
    const float* n2_s    = (const float*)d_in[18];
    const float* n2_b    = (const float*)d_in[19];
    const float* mlp_w1  = (const float*)d_in[20];
    const float* mlp_b1  = (const float*)d_in[21];
    const float* mlp_w2  = (const float*)d_in[22];
    const float* mlp_b2  = (const float*)d_in[23];
    const float* no_s    = (const float*)d_in[24];
    const float* no_b    = (const float*)d_in[25];
    const float* head_w  = (const float*)d_in[26];
    const float* head_b  = (const float*)d_in[27];
    float* out = (float*)d_out;

    float *px, *ph, *pxp, *pz, *pp, *py, *pmlp;
    cudaGetSymbolAddress((void**)&px,   g_x);
    cudaGetSymbolAddress((void**)&ph,   g_h);
    cudaGetSymbolAddress((void**)&pxp,  g_xp);
    cudaGetSymbolAddress((void**)&pz,   g_z);
    cudaGetSymbolAddress((void**)&pp,   g_p);
    cudaGetSymbolAddress((void**)&py,   g_y);
    cudaGetSymbolAddress((void**)&pmlp, g_mlp);

    // time embedding + token embedding
    time_feat_kernel<<<1, EMBEDD>>>(t);
    time_mlp1_kernel<<<(BBATCH * MLPDIM + 255) / 256, 256>>>(time_w1, time_b1);
    time_mlp2_kernel<<<(BBATCH * EMBEDD + 255) / 256, 256>>>(time_w2, time_b2);
    embed_kernel<<<ROWS, EMBEDD>>>(tokens, tok_emb);

    dim3 gE((EMBEDD + 63) / 64, ROWS / 64);       // 64-tile, N=512  (grid 8x32)
    dim3 gP((PDIM   + 63) / 64, ROWS / 64);       // 64-tile, N=64   (grid 1x32)
    dim3 gM((MLPDIM + 127) / 128, ROWS / 128);    // 128-tile, N=2048 (grid 16x16)
    dim3 gV((VOCABN + 127) / 128, ROWS / 128);    // 128-tile, N=50000 (grid 391x16)

    for (int i = 0; i < DEPTHN; i++) {
        // ln1
        ln_kernel<<<ROWS, EMBEDD>>>(px, ph, n1_s + i * EMBEDD, n1_b + i * EMBEDD);
        // fused xp/z projections (shared A tiles)
        gemm2_kernel<<<gE, 256>>>(ph, wx + (size_t)i * EMBEDD * EMBEDD,
                                      wz + (size_t)i * EMBEDD * EMBEDD,
                                      pxp, pz, ROWS, EMBEDD, EMBEDD);
        // p projection
        gemm_kernel<<<gP, 256>>>(ph, wp + (size_t)i * EMBEDD * PDIM,   nullptr, nullptr, pp,  ROWS, PDIM,   EMBEDD, 0);
        // dt projection + softplus
        dt_kernel<<<ROWS, EMBEDD>>>(dt_w + (size_t)i * DTRN * EMBEDD, dt_b + i * EMBEDD);
        // causal depthwise conv + silu
        conv_kernel<<<ROWS, EMBEDD>>>(conv_w + (size_t)i * EMBEDD * DCONVN);
        // selective scan + gate (smem-staged)
        scan_kernel<<<BBATCH * (EMBEDD / 8), 128>>>(A_log + (size_t)i * EMBEDD * NSTATE,
                                                    Dparam + i * EMBEDD);
        // out projection + residual (x = x + y @ wo)
        gemm_kernel<<<gE, 256>>>(py, wo + (size_t)i * EMBEDD * EMBEDD, nullptr, px, px, ROWS, EMBEDD, EMBEDD, 0);
        // ln2 + MLP
        ln_kernel<<<ROWS, EMBEDD>>>(px, ph, n2_s + i * EMBEDD, n2_b + i * EMBEDD);
        bfgemm_kernel<<<gM, 256>>>(ph, mlp_w1 + (size_t)i * EMBEDD * MLPDIM, mlp_b1 + i * MLPDIM, pmlp, ROWS, MLPDIM, EMBEDD, 1);
        gemm_kernel<<<gE, 256>>>(pmlp, mlp_w2 + (size_t)i * MLPDIM * EMBEDD, mlp_b2 + i * EMBEDD, px, px, ROWS, EMBEDD, MLPDIM, 0);
    }

    // final LN + vocab head (3xBF16 tensor GEMM)
    ln_kernel<<<ROWS, EMBEDD>>>(px, ph, no_s, no_b);
    bfgemm_kernel<<<gV, 256>>>(ph, head_w, head_b, out, ROWS, VOCABN, EMBEDD, 0);
}